// round 5
// baseline (speedup 1.0000x reference)
#include <cuda_runtime.h>
#include <cstdint>
#include <cstddef>

#define T_STEPS    64
#define INPUT_BITS 1024
#define N_STATE    2048
#define N_OUT      256
#define HASH       65536

#define CLUSTER_CTAS 8
#define CTA_THREADS  256                 // 8 * 256 = 2048 -> one thread per state neuron

// Unified smem bit store (per CTA):
//   words [0, 2048)      : packed window bits, 32 words per step t (all 64 steps)
//   words [2048, 2112)   : state buffer 0 (64 words)
//   words [2112, 2176)   : state buffer 1 (64 words)
#define WIN_WORDS   2048
#define STATE_BASE  2048
#define SBITS_WORDS 2176
#define STEP_TX_BYTES 256                // 64 words * 4B arrive per CTA per step

// -------- helpers ------------------------------------------------------------
__device__ __forceinline__ uint32_t smem_u32(const void* p) {
    uint32_t a;
    asm("{ .reg .u64 t; cvta.to.shared.u64 t, %1; cvt.u32.u64 %0, t; }"
        : "=r"(a) : "l"(p));
    return a;
}
__device__ __forceinline__ uint32_t cluster_rank() {
    uint32_t r;
    asm("mov.u32 %0, %%cluster_ctarank;" : "=r"(r));
    return r;
}
__device__ __forceinline__ uint32_t mapa_u32(uint32_t laddr, uint32_t rank) {
    uint32_t raddr;
    asm("mapa.shared::cluster.u32 %0, %1, %2;" : "=r"(raddr) : "r"(laddr), "r"(rank));
    return raddr;
}
// Remote smem store that signals the remote mbarrier with 4 tx bytes on arrival.
__device__ __forceinline__ void st_async_u32(uint32_t rdata, unsigned v, uint32_t rmbar) {
    asm volatile(
        "st.async.shared::cluster.mbarrier::complete_tx::bytes.b32 [%0], %1, [%2];"
        :: "r"(rdata), "r"(v), "r"(rmbar) : "memory");
}
__device__ __forceinline__ void mbar_init(uint32_t mbar, unsigned count) {
    asm volatile("mbarrier.init.shared.b64 [%0], %1;" :: "r"(mbar), "r"(count) : "memory");
}
__device__ __forceinline__ void mbar_arrive(uint32_t mbar) {
    asm volatile("mbarrier.arrive.shared.b64 _, [%0];" :: "r"(mbar) : "memory");
}
__device__ __forceinline__ void mbar_arm_tx(uint32_t mbar, unsigned tx) {
    asm volatile("mbarrier.arrive.expect_tx.shared.b64 _, [%0], %1;"
                 :: "r"(mbar), "r"(tx) : "memory");
}
__device__ __forceinline__ void mbar_wait_parity(uint32_t mbar, unsigned parity) {
    unsigned done;
    asm volatile(
        "{\n\t.reg .pred p;\n\t"
        "mbarrier.try_wait.parity.acquire.cta.shared::cta.b64 p, [%1], %2;\n\t"
        "selp.b32 %0, 1, 0, p;\n\t}"
        : "=r"(done) : "r"(mbar), "r"(parity) : "memory");
    if (!done) {
        asm volatile(
            "{\n\t.reg .pred P1;\n\t"
            "WAIT_LOOP_%=:\n\t"
            "mbarrier.try_wait.parity.acquire.cta.shared::cta.b64 P1, [%0], %1, 0x989680;\n\t"
            "@P1 bra.uni WAIT_DONE_%=;\n\t"
            "bra.uni WAIT_LOOP_%=;\n\t"
            "WAIT_DONE_%=:\n\t}"
            :: "r"(mbar), "r"(parity) : "memory");
    }
}
#define CLUSTER_SYNC() do {                                              \
    asm volatile("barrier.cluster.arrive.aligned;" ::: "memory");        \
    asm volatile("barrier.cluster.wait.aligned;"   ::: "memory");        \
} while (0)

// ---------------------------------------------------------------------------
__global__ __launch_bounds__(CTA_THREADS)
__cluster_dims__(CLUSTER_CTAS, 1, 1)
void recurrent_kernel(
    const int*   __restrict__ input_bits,
    const int*   __restrict__ conn_state,
    const float* __restrict__ state_table,
    const int*   __restrict__ conn_out,
    const float* __restrict__ output_table,
    float*       __restrict__ out)
{
    __shared__ unsigned sbits[SBITS_WORDS];
    __shared__ __align__(8) unsigned long long mbar[2];

    const int tid  = threadIdx.x;
    const int lane = tid & 31;
    const int warp = tid >> 5;                    // 0..7
    const uint32_t rank = cluster_rank();
    const int n = (int)rank * CTA_THREADS + tid;  // my state neuron

    const uint32_t sb = smem_u32(sbits);
    const uint32_t mb = smem_u32(mbar);

    // ---- startup: pack all 64 windows into smem, one word per (thread,k) ----
#pragma unroll
    for (int k = 0; k < 8; k++) {
        const int W = k * CTA_THREADS + tid;           // 0..2047
        const int4* p = reinterpret_cast<const int4*>(input_bits) + W * 8;
        unsigned bword = 0;
#pragma unroll
        for (int q = 0; q < 8; q++) {
            const int4 v = p[q];
            bword |= ((unsigned)v.x << (q * 4 + 0))
                   | ((unsigned)v.y << (q * 4 + 1))
                   | ((unsigned)v.z << (q * 4 + 2))
                   | ((unsigned)v.w << (q * 4 + 3));
        }
        sbits[W] = bword;
    }
    // zero both state buffers (t=0 reads buffer 0 => all-zero initial state)
    if (tid < 128) sbits[STATE_BASE + tid] = 0u;

    // ---- mbarrier setup: arm = 1 arrive + 256 tx bytes per phase ------------
    if (tid == 0) {
        mbar_init(mb + 0, 1);
        mbar_init(mb + 8, 1);
        mbar_arrive(mb + 0);                 // burn phase 0 of mbar[0] (no step-0 wait)
        mbar_arm_tx(mb + 0, STEP_TX_BYTES);  // arm mbar[0] phase 1  -> step 2
        mbar_arm_tx(mb + 8, STEP_TX_BYTES);  // arm mbar[1] phase 0  -> step 1
    }

    // ---- preload my 16 connections, encoded as (word_index<<5 | shift) ------
    int enc[16];
    {
        const int4* c4 = reinterpret_cast<const int4*>(conn_state) + n * 4;
        int4 a0 = c4[0], a1 = c4[1], a2 = c4[2], a3 = c4[3];
        int raw[16] = { a0.x,a0.y,a0.z,a0.w, a1.x,a1.y,a1.z,a1.w,
                        a2.x,a2.y,a2.z,a2.w, a3.x,a3.y,a3.z,a3.w };
#pragma unroll
        for (int j = 0; j < 16; j++) {
            const int ci = raw[j];
            const int sh = ci & 31;
            const int base = (ci < INPUT_BITS) ? (ci >> 5)
                                               : (STATE_BASE + ((ci - INPUT_BITS) >> 5));
            enc[j] = (base << 5) | sh;
        }
    }
    const float* trow = state_table + (size_t)n * HASH;

    __syncthreads();        // smem init complete within CTA
    CLUSTER_SYNC();         // all CTAs' smem + armed mbarriers visible cluster-wide

    // Window partial address for step 0 (static smem, no sync needed).
    unsigned accw = 0u;
#pragma unroll
    for (int j = 0; j < 16; j++) {
        const int e = enc[j], base = e >> 5;
        if (base < STATE_BASE)                       // window connection
            accw |= ((sbits[base] >> (e & 31)) & 1u) << j;   // woff(t=0) = 0
    }

    // ---- recurrence: 64 steps; wait = arrival of 64 state words -------------
    for (int t = 0; t < T_STEPS; t++) {
        if (t > 0) {
            const uint32_t m = mb + ((unsigned)(t & 1) << 3);
            mbar_wait_parity(m, (unsigned)(t >> 1) & 1u);
            if (tid == 0)
                mbar_arm_tx(m, STEP_TX_BYTES);       // re-arm for step t+2
        }

        // post-wakeup: only the ~2/3 state connections
        const int boff = (t & 1) << 6;               // state read-buffer offset
        unsigned acc = accw;
#pragma unroll
        for (int j = 0; j < 16; j++) {
            const int e = enc[j], base = e >> 5;
            if (base >= STATE_BASE)                  // state connection
                acc |= ((sbits[base + boff] >> (e & 31)) & 1u) << j;
        }

        const float v = __ldg(trow + acc);
        const unsigned bal = __ballot_sync(0xffffffffu, v > 0.5f);

        // push my warp's ballot word into ALL 8 CTAs' next-state buffer;
        // each store signals the destination's mbarrier (+4 tx bytes).
        if (lane < CLUSTER_CTAS) {
            const uint32_t widx  = (uint32_t)(STATE_BASE + (((t + 1) & 1) << 6))
                                 + rank * 8u + (uint32_t)warp;
            const uint32_t laddr = sb + (widx << 2);
            const uint32_t lmbar = mb + ((unsigned)((t + 1) & 1) << 3);
            st_async_u32(mapa_u32(laddr, (uint32_t)lane), bal,
                         mapa_u32(lmbar, (uint32_t)lane));
        }

        // window partial for step t+1 — overlaps the next mbarrier wait
        if (t + 1 < T_STEPS) {
            const int woff = (t + 1) << 5;
            accw = 0u;
#pragma unroll
            for (int j = 0; j < 16; j++) {
                const int e = enc[j], base = e >> 5;
                if (base < STATE_BASE)
                    accw |= ((sbits[base + woff] >> (e & 31)) & 1u) << j;
            }
        }
    }

    // ---- final wait: no CTA exits with incoming st.async in flight ----------
    // step "64": mbar[0], phase 32 -> parity 0; final state lands in buffer 0.
    mbar_wait_parity(mb + 0, 0u);

    if (rank == 0) {
        const int o = tid;                                 // 0..255
        const int4* c4 = reinterpret_cast<const int4*>(conn_out) + o * 4;
        int4 a0 = c4[0], a1 = c4[1], a2 = c4[2], a3 = c4[3];
        int co[16] = { a0.x,a0.y,a0.z,a0.w, a1.x,a1.y,a1.z,a1.w,
                       a2.x,a2.y,a2.z,a2.w, a3.x,a3.y,a3.z,a3.w };
        unsigned addr = 0;
#pragma unroll
        for (int j = 0; j < 16; j++) {
            const int ci = co[j];
            addr |= ((sbits[STATE_BASE + (ci >> 5)] >> (ci & 31)) & 1u) << j;
        }
        out[o] = __ldg(output_table + (size_t)o * HASH + addr);
    }
}

// ---------------------------------------------------------------------------
extern "C" void kernel_launch(void* const* d_in, const int* in_sizes, int n_in,
                              void* d_out, int out_size)
{
    const int*   input_bits   = (const int*)  d_in[0];  // [65536]
    const int*   conn_state   = (const int*)  d_in[1];  // [2048*16]
    const int*   conn_out     = (const int*)  d_in[2];  // [256*16]
    const float* state_table  = (const float*)d_in[3];  // [2048*65536]
    const float* output_table = (const float*)d_in[4];  // [256*65536]
    float*       out          = (float*)d_out;          // [256]

    recurrent_kernel<<<CLUSTER_CTAS, CTA_THREADS>>>(
        input_bits, conn_state, state_table, conn_out, output_table, out);
}

// round 6
// speedup vs baseline: 1.9863x; 1.9863x over previous
#include <cuda_runtime.h>
#include <cstdint>
#include <cstddef>

#define T_STEPS    64
#define INPUT_BITS 1024
#define N_STATE    2048
#define N_OUT      256
#define HASH       65536

#define CLUSTER_CTAS 8
#define CTA_THREADS  256                 // 8 * 256 = 2048 -> one thread per state neuron

// Unified smem bit store (per CTA):
//   words [0, 2048)      : packed window bits, 32 words per step t (all 64 steps)
//   words [2048, 2112)   : state buffer 0 (64 words)
//   words [2112, 2176)   : state buffer 1 (64 words)
#define WIN_WORDS   2048
#define STATE_BASE  2048
#define SBITS_WORDS 2176
#define STEP_TX_BYTES 256                // 64 words * 4B arrive per CTA per step

// -------- helpers ------------------------------------------------------------
__device__ __forceinline__ uint32_t smem_u32(const void* p) {
    uint32_t a;
    asm("{ .reg .u64 t; cvta.to.shared.u64 t, %1; cvt.u32.u64 %0, t; }"
        : "=r"(a) : "l"(p));
    return a;
}
__device__ __forceinline__ uint32_t cluster_rank() {
    uint32_t r;
    asm("mov.u32 %0, %%cluster_ctarank;" : "=r"(r));
    return r;
}
__device__ __forceinline__ uint32_t mapa_u32(uint32_t laddr, uint32_t rank) {
    uint32_t raddr;
    asm("mapa.shared::cluster.u32 %0, %1, %2;" : "=r"(raddr) : "r"(laddr), "r"(rank));
    return raddr;
}
// Remote smem store that signals the remote mbarrier with 4 tx bytes on arrival.
__device__ __forceinline__ void st_async_u32(uint32_t rdata, unsigned v, uint32_t rmbar) {
    asm volatile(
        "st.async.shared::cluster.mbarrier::complete_tx::bytes.b32 [%0], %1, [%2];"
        :: "r"(rdata), "r"(v), "r"(rmbar) : "memory");
}
__device__ __forceinline__ void mbar_init(uint32_t mbar, unsigned count) {
    asm volatile("mbarrier.init.shared.b64 [%0], %1;" :: "r"(mbar), "r"(count) : "memory");
}
__device__ __forceinline__ void mbar_arrive(uint32_t mbar) {
    asm volatile("mbarrier.arrive.shared.b64 _, [%0];" :: "r"(mbar) : "memory");
}
__device__ __forceinline__ void mbar_arm_tx(uint32_t mbar, unsigned tx) {
    asm volatile("mbarrier.arrive.expect_tx.shared.b64 _, [%0], %1;"
                 :: "r"(mbar), "r"(tx) : "memory");
}
__device__ __forceinline__ void mbar_wait_parity(uint32_t mbar, unsigned parity) {
    unsigned done;
    asm volatile(
        "{\n\t.reg .pred p;\n\t"
        "mbarrier.try_wait.parity.acquire.cta.shared::cta.b64 p, [%1], %2;\n\t"
        "selp.b32 %0, 1, 0, p;\n\t}"
        : "=r"(done) : "r"(mbar), "r"(parity) : "memory");
    if (!done) {
        asm volatile(
            "{\n\t.reg .pred P1;\n\t"
            "WAIT_LOOP_%=:\n\t"
            "mbarrier.try_wait.parity.acquire.cta.shared::cta.b64 P1, [%0], %1, 0x989680;\n\t"
            "@P1 bra.uni WAIT_DONE_%=;\n\t"
            "bra.uni WAIT_LOOP_%=;\n\t"
            "WAIT_DONE_%=:\n\t}"
            :: "r"(mbar), "r"(parity) : "memory");
    }
}
#define CLUSTER_SYNC() do {                                              \
    asm volatile("barrier.cluster.arrive.aligned;" ::: "memory");        \
    asm volatile("barrier.cluster.wait.aligned;"   ::: "memory");        \
} while (0)

// ---------------------------------------------------------------------------
__global__ __launch_bounds__(CTA_THREADS)
__cluster_dims__(CLUSTER_CTAS, 1, 1)
void recurrent_kernel(
    const int*   __restrict__ input_bits,
    const int*   __restrict__ conn_state,
    const float* __restrict__ state_table,
    const int*   __restrict__ conn_out,
    const float* __restrict__ output_table,
    float*       __restrict__ out)
{
    __shared__ unsigned sbits[SBITS_WORDS];
    __shared__ __align__(8) unsigned long long mbar[2];

    const int tid  = threadIdx.x;
    const int lane = tid & 31;
    const int warp = tid >> 5;                    // 0..7
    const uint32_t rank = cluster_rank();
    const int n = (int)rank * CTA_THREADS + tid;  // my state neuron

    const uint32_t sb = smem_u32(sbits);
    const uint32_t mb = smem_u32(mbar);

    // ---- startup: pack all 64 windows into smem, one word per (thread,k) ----
#pragma unroll
    for (int k = 0; k < 8; k++) {
        const int W = k * CTA_THREADS + tid;           // 0..2047
        const int4* p = reinterpret_cast<const int4*>(input_bits) + W * 8;
        unsigned bword = 0;
#pragma unroll
        for (int q = 0; q < 8; q++) {
            const int4 v = p[q];
            bword |= ((unsigned)v.x << (q * 4 + 0))
                   | ((unsigned)v.y << (q * 4 + 1))
                   | ((unsigned)v.z << (q * 4 + 2))
                   | ((unsigned)v.w << (q * 4 + 3));
        }
        sbits[W] = bword;
    }
    // zero both state buffers (t=0 reads buffer 0 => all-zero initial state)
    if (tid < 128) sbits[STATE_BASE + tid] = 0u;

    // ---- mbarrier setup: arm = 1 arrive + 256 tx bytes per phase ------------
    if (tid == 0) {
        mbar_init(mb + 0, 1);
        mbar_init(mb + 8, 1);
        mbar_arrive(mb + 0);                 // burn phase 0 of mbar[0] (no step-0 wait)
        mbar_arm_tx(mb + 0, STEP_TX_BYTES);  // arm mbar[0] phase 1  -> step 2
        mbar_arm_tx(mb + 8, STEP_TX_BYTES);  // arm mbar[1] phase 0  -> step 1
    }

    // ---- preload my 16 connections, encoded as (word_index<<5 | shift) ------
    int enc[16];
    {
        const int4* c4 = reinterpret_cast<const int4*>(conn_state) + n * 4;
        int4 a0 = c4[0], a1 = c4[1], a2 = c4[2], a3 = c4[3];
        int raw[16] = { a0.x,a0.y,a0.z,a0.w, a1.x,a1.y,a1.z,a1.w,
                        a2.x,a2.y,a2.z,a2.w, a3.x,a3.y,a3.z,a3.w };
#pragma unroll
        for (int j = 0; j < 16; j++) {
            const int ci = raw[j];
            const int sh = ci & 31;
            const int base = (ci < INPUT_BITS) ? (ci >> 5)
                                               : (STATE_BASE + ((ci - INPUT_BITS) >> 5));
            enc[j] = (base << 5) | sh;
        }
    }
    const float* trow = state_table + (size_t)n * HASH;

    // ---- precompute push targets for both parities (lanes 0..7 only) --------
    // destination word for parity p: STATE_BASE + p*64 + rank*8 + warp, in CTA `lane`
    uint32_t rdata0 = 0, rdata1 = 0, rmbar0 = 0, rmbar1 = 0;
    if (lane < CLUSTER_CTAS) {
        const uint32_t w0 = (uint32_t)(STATE_BASE + 0)  + rank * 8u + (uint32_t)warp;
        const uint32_t w1 = (uint32_t)(STATE_BASE + 64) + rank * 8u + (uint32_t)warp;
        rdata0 = mapa_u32(sb + (w0 << 2), (uint32_t)lane);
        rdata1 = mapa_u32(sb + (w1 << 2), (uint32_t)lane);
        rmbar0 = mapa_u32(mb + 0, (uint32_t)lane);
        rmbar1 = mapa_u32(mb + 8, (uint32_t)lane);
    }

    __syncthreads();        // smem init complete within CTA
    CLUSTER_SYNC();         // all CTAs' smem + armed mbarriers visible cluster-wide

    // ---- step 0 (peeled: no wait, state is all zeros, boff = 0) -------------
    {
        unsigned acc = 0;
#pragma unroll
        for (int j = 0; j < 16; j++) {
            const int e    = enc[j];
            const int base = e >> 5;
            const int idx  = base + ((base < STATE_BASE) ? 0 : 0);  // woff(0)=0, boff=0
            acc |= ((sbits[idx] >> (e & 31)) & 1u) << j;
        }
        const float v = __ldg(trow + acc);
        const unsigned bal = __ballot_sync(0xffffffffu, v > 0.5f);
        if (lane < CLUSTER_CTAS)
            st_async_u32(rdata1, bal, rmbar1);       // t+1 = 1 -> buffer 1 / mbar 1
    }

    // ---- steps 1..63: wait = arrival of 64 state words ----------------------
    for (int t = 1; t < T_STEPS; t++) {
        const uint32_t m = mb + ((unsigned)(t & 1) << 3);
        mbar_wait_parity(m, (unsigned)(t >> 1) & 1u);

        const int woff = t << 5;                     // window word offset
        const int boff = (t & 1) << 6;               // state read-buffer offset

        unsigned acc = 0;
#pragma unroll
        for (int j = 0; j < 16; j++) {
            const int e    = enc[j];
            const int base = e >> 5;
            const int idx  = base + ((base < STATE_BASE) ? woff : boff);
            acc |= ((sbits[idx] >> (e & 31)) & 1u) << j;
        }

        const float v = __ldg(trow + acc);
        const unsigned bal = __ballot_sync(0xffffffffu, v > 0.5f);

        // re-arm for step t+2 (after ballot: off the gather/LDG path; still
        // program-ordered before lane 0's push, which peers need to reach t+2)
        if (tid == 0)
            mbar_arm_tx(m, STEP_TX_BYTES);

        // push my warp's ballot word into ALL 8 CTAs' next-state buffer
        if (lane < CLUSTER_CTAS) {
            const unsigned p1 = (unsigned)((t + 1) & 1);
            st_async_u32(p1 ? rdata1 : rdata0, bal, p1 ? rmbar1 : rmbar0);
        }
    }

    // ---- final wait: no CTA exits with incoming st.async in flight ----------
    // step "64": mbar[0], phase 32 -> parity 0; final state lands in buffer 0.
    mbar_wait_parity(mb + 0, 0u);

    if (rank == 0) {
        const int o = tid;                                 // 0..255
        const int4* c4 = reinterpret_cast<const int4*>(conn_out) + o * 4;
        int4 a0 = c4[0], a1 = c4[1], a2 = c4[2], a3 = c4[3];
        int co[16] = { a0.x,a0.y,a0.z,a0.w, a1.x,a1.y,a1.z,a1.w,
                       a2.x,a2.y,a2.z,a2.w, a3.x,a3.y,a3.z,a3.w };
        unsigned addr = 0;
#pragma unroll
        for (int j = 0; j < 16; j++) {
            const int ci = co[j];
            addr |= ((sbits[STATE_BASE + (ci >> 5)] >> (ci & 31)) & 1u) << j;
        }
        out[o] = __ldg(output_table + (size_t)o * HASH + addr);
    }
}

// ---------------------------------------------------------------------------
extern "C" void kernel_launch(void* const* d_in, const int* in_sizes, int n_in,
                              void* d_out, int out_size)
{
    const int*   input_bits   = (const int*)  d_in[0];  // [65536]
    const int*   conn_state   = (const int*)  d_in[1];  // [2048*16]
    const int*   conn_out     = (const int*)  d_in[2];  // [256*16]
    const float* state_table  = (const float*)d_in[3];  // [2048*65536]
    const float* output_table = (const float*)d_in[4];  // [256*65536]
    float*       out          = (float*)d_out;          // [256]

    recurrent_kernel<<<CLUSTER_CTAS, CTA_THREADS>>>(
        input_bits, conn_state, state_table, conn_out, output_table, out);
}

// round 7
// speedup vs baseline: 2.0104x; 1.0121x over previous
#include <cuda_runtime.h>
#include <cstdint>
#include <cstddef>

#define T_STEPS    64
#define INPUT_BITS 1024
#define N_STATE    2048
#define N_OUT      256
#define HASH       65536

// Unified smem bit store (per CTA):
//   words [0, 2048)      : packed window bits, 32 words per step t (all 64 steps)
//   words [2048, 2112)   : state buffer 0 (64 words)
//   words [2112, 2176)   : state buffer 1 (64 words)
#define WIN_WORDS   2048
#define STATE_BASE  2048
#define SBITS_WORDS 2176
#define STEP_TX_BYTES 256                // 64 words * 4B arrive per CTA per step

// -------- helpers ------------------------------------------------------------
__device__ __forceinline__ uint32_t smem_u32(const void* p) {
    uint32_t a;
    asm("{ .reg .u64 t; cvta.to.shared.u64 t, %1; cvt.u32.u64 %0, t; }"
        : "=r"(a) : "l"(p));
    return a;
}
__device__ __forceinline__ uint32_t cluster_rank() {
    uint32_t r;
    asm("mov.u32 %0, %%cluster_ctarank;" : "=r"(r));
    return r;
}
__device__ __forceinline__ uint32_t mapa_u32(uint32_t laddr, uint32_t rank) {
    uint32_t raddr;
    asm("mapa.shared::cluster.u32 %0, %1, %2;" : "=r"(raddr) : "r"(laddr), "r"(rank));
    return raddr;
}
// Remote smem store that signals the remote mbarrier with 4 tx bytes on arrival.
__device__ __forceinline__ void st_async_u32(uint32_t rdata, unsigned v, uint32_t rmbar) {
    asm volatile(
        "st.async.shared::cluster.mbarrier::complete_tx::bytes.b32 [%0], %1, [%2];"
        :: "r"(rdata), "r"(v), "r"(rmbar) : "memory");
}
__device__ __forceinline__ void mbar_init(uint32_t mbar, unsigned count) {
    asm volatile("mbarrier.init.shared.b64 [%0], %1;" :: "r"(mbar), "r"(count) : "memory");
}
__device__ __forceinline__ void mbar_arrive(uint32_t mbar) {
    asm volatile("mbarrier.arrive.shared.b64 _, [%0];" :: "r"(mbar) : "memory");
}
__device__ __forceinline__ void mbar_arm_tx(uint32_t mbar, unsigned tx) {
    asm volatile("mbarrier.arrive.expect_tx.shared.b64 _, [%0], %1;"
                 :: "r"(mbar), "r"(tx) : "memory");
}
__device__ __forceinline__ void mbar_wait_parity(uint32_t mbar, unsigned parity) {
    unsigned done;
    asm volatile(
        "{\n\t.reg .pred p;\n\t"
        "mbarrier.try_wait.parity.acquire.cta.shared::cta.b64 p, [%1], %2;\n\t"
        "selp.b32 %0, 1, 0, p;\n\t}"
        : "=r"(done) : "r"(mbar), "r"(parity) : "memory");
    if (!done) {
        asm volatile(
            "{\n\t.reg .pred P1;\n\t"
            "WAIT_LOOP_%=:\n\t"
            "mbarrier.try_wait.parity.acquire.cta.shared::cta.b64 P1, [%0], %1, 0x989680;\n\t"
            "@P1 bra.uni WAIT_DONE_%=;\n\t"
            "bra.uni WAIT_LOOP_%=;\n\t"
            "WAIT_DONE_%=:\n\t}"
            :: "r"(mbar), "r"(parity) : "memory");
    }
}
#define CLUSTER_SYNC() do {                                              \
    asm volatile("barrier.cluster.arrive.aligned;" ::: "memory");        \
    asm volatile("barrier.cluster.wait.aligned;"   ::: "memory");        \
} while (0)

// ---------------------------------------------------------------------------
// NCTAS x THREADS = 2048 threads = 2048 state neurons. Protocol identical for
// any cluster size: each warp owns one state word (global word = rank*WPC+warp)
// and pushes it to every CTA via st.async; a CTA's step mbarrier completes when
// all 64 words (256 tx bytes) have landed.
template<int NCTAS, int THREADS>
__global__ __launch_bounds__(THREADS) void recurrent_kernel(
    const int*   __restrict__ input_bits,
    const int*   __restrict__ conn_state,
    const float* __restrict__ state_table,
    const int*   __restrict__ conn_out,
    const float* __restrict__ output_table,
    float*       __restrict__ out)
{
    constexpr int WPC = THREADS / 32;     // warps (state words) per CTA

    __shared__ unsigned sbits[SBITS_WORDS];
    __shared__ __align__(8) unsigned long long mbar[2];

    const int tid  = threadIdx.x;
    const int lane = tid & 31;
    const int warp = tid >> 5;
    const uint32_t rank = cluster_rank();
    const int n = (int)rank * THREADS + tid;      // my state neuron

    const uint32_t sb = smem_u32(sbits);
    const uint32_t mb = smem_u32(mbar);

    // ---- startup: pack all 64 windows into smem, one word per (thread,k) ----
#pragma unroll
    for (int k = 0; k < WIN_WORDS / THREADS; k++) {
        const int W = k * THREADS + tid;           // 0..2047
        const int4* p = reinterpret_cast<const int4*>(input_bits) + W * 8;
        unsigned bword = 0;
#pragma unroll
        for (int q = 0; q < 8; q++) {
            const int4 v = p[q];
            bword |= ((unsigned)v.x << (q * 4 + 0))
                   | ((unsigned)v.y << (q * 4 + 1))
                   | ((unsigned)v.z << (q * 4 + 2))
                   | ((unsigned)v.w << (q * 4 + 3));
        }
        sbits[W] = bword;
    }
    // zero both state buffers (t=0 reads buffer 0 => all-zero initial state)
    if (tid < 128) sbits[STATE_BASE + tid] = 0u;

    // ---- mbarrier setup: arm = 1 arrive + 256 tx bytes per phase ------------
    if (tid == 0) {
        mbar_init(mb + 0, 1);
        mbar_init(mb + 8, 1);
        mbar_arrive(mb + 0);                 // burn phase 0 of mbar[0] (no step-0 wait)
        mbar_arm_tx(mb + 0, STEP_TX_BYTES);  // arm mbar[0] phase 1  -> step 2
        mbar_arm_tx(mb + 8, STEP_TX_BYTES);  // arm mbar[1] phase 0  -> step 1
    }

    // ---- preload my 16 connections, encoded as (word_index<<5 | shift) ------
    int enc[16];
    {
        const int4* c4 = reinterpret_cast<const int4*>(conn_state) + n * 4;
        int4 a0 = c4[0], a1 = c4[1], a2 = c4[2], a3 = c4[3];
        int raw[16] = { a0.x,a0.y,a0.z,a0.w, a1.x,a1.y,a1.z,a1.w,
                        a2.x,a2.y,a2.z,a2.w, a3.x,a3.y,a3.z,a3.w };
#pragma unroll
        for (int j = 0; j < 16; j++) {
            const int ci = raw[j];
            const int sh = ci & 31;
            const int base = (ci < INPUT_BITS) ? (ci >> 5)
                                               : (STATE_BASE + ((ci - INPUT_BITS) >> 5));
            enc[j] = (base << 5) | sh;
        }
    }
    const float* trow = state_table + (size_t)n * HASH;

    // ---- precompute push targets for both parities (lanes 0..NCTAS-1) -------
    uint32_t rdata0 = 0, rdata1 = 0, rmbar0 = 0, rmbar1 = 0;
    if (lane < NCTAS) {
        const uint32_t w0 = (uint32_t)(STATE_BASE + 0)  + rank * (uint32_t)WPC + (uint32_t)warp;
        const uint32_t w1 = (uint32_t)(STATE_BASE + 64) + rank * (uint32_t)WPC + (uint32_t)warp;
        rdata0 = mapa_u32(sb + (w0 << 2), (uint32_t)lane);
        rdata1 = mapa_u32(sb + (w1 << 2), (uint32_t)lane);
        rmbar0 = mapa_u32(mb + 0, (uint32_t)lane);
        rmbar1 = mapa_u32(mb + 8, (uint32_t)lane);
    }

    __syncthreads();        // smem init complete within CTA
    CLUSTER_SYNC();         // all CTAs' smem + armed mbarriers visible cluster-wide

    // ---- step 0 (peeled: no wait, state all zeros, woff = boff = 0) ---------
    {
        unsigned acc = 0;
#pragma unroll
        for (int j = 0; j < 16; j++) {
            const int e = enc[j];
            acc |= ((sbits[e >> 5] >> (e & 31)) & 1u) << j;
        }
        const float v = __ldg(trow + acc);
        const unsigned bal = __ballot_sync(0xffffffffu, v > 0.5f);
        if (lane < NCTAS)
            st_async_u32(rdata1, bal, rmbar1);       // t+1 = 1 -> buffer 1 / mbar 1
    }

    // ---- steps 1..63: wait = arrival of all 64 state words -------------------
    for (int t = 1; t < T_STEPS; t++) {
        const uint32_t m = mb + ((unsigned)(t & 1) << 3);
        mbar_wait_parity(m, (unsigned)(t >> 1) & 1u);

        const int woff = t << 5;                     // window word offset
        const int boff = (t & 1) << 6;               // state read-buffer offset

        unsigned acc = 0;
#pragma unroll
        for (int j = 0; j < 16; j++) {
            const int e    = enc[j];
            const int base = e >> 5;
            const int idx  = base + ((base < STATE_BASE) ? woff : boff);
            acc |= ((sbits[idx] >> (e & 31)) & 1u) << j;
        }

        const float v = __ldg(trow + acc);
        const unsigned bal = __ballot_sync(0xffffffffu, v > 0.5f);

        // re-arm for step t+2 (off the gather/LDG path; still program-ordered
        // before lane 0's push, which peers need before any t+2 store arrives)
        if (tid == 0)
            mbar_arm_tx(m, STEP_TX_BYTES);

        // push my warp's ballot word into ALL cluster CTAs' next-state buffer
        if (lane < NCTAS) {
            const unsigned p1 = (unsigned)((t + 1) & 1);
            st_async_u32(p1 ? rdata1 : rdata0, bal, p1 ? rmbar1 : rmbar0);
        }
    }

    // ---- final wait: no CTA exits with incoming st.async in flight ----------
    // step "64": mbar[0], phase 32 -> parity 0; final state lands in buffer 0.
    mbar_wait_parity(mb + 0, 0u);

    if (rank == 0) {
        for (int o = tid; o < N_OUT; o += THREADS) {
            const int4* c4 = reinterpret_cast<const int4*>(conn_out) + o * 4;
            int4 a0 = c4[0], a1 = c4[1], a2 = c4[2], a3 = c4[3];
            int co[16] = { a0.x,a0.y,a0.z,a0.w, a1.x,a1.y,a1.z,a1.w,
                           a2.x,a2.y,a2.z,a2.w, a3.x,a3.y,a3.z,a3.w };
            unsigned addr = 0;
#pragma unroll
            for (int j = 0; j < 16; j++) {
                const int ci = co[j];
                addr |= ((sbits[STATE_BASE + (ci >> 5)] >> (ci & 31)) & 1u) << j;
            }
            out[o] = __ldg(output_table + (size_t)o * HASH + addr);
        }
    }
}

// ---------------------------------------------------------------------------
extern "C" void kernel_launch(void* const* d_in, const int* in_sizes, int n_in,
                              void* d_out, int out_size)
{
    const int*   input_bits   = (const int*)  d_in[0];  // [65536]
    const int*   conn_state   = (const int*)  d_in[1];  // [2048*16]
    const int*   conn_out     = (const int*)  d_in[2];  // [256*16]
    const float* state_table  = (const float*)d_in[3];  // [2048*65536]
    const float* output_table = (const float*)d_in[4];  // [256*65536]
    float*       out          = (float*)d_out;          // [256]

    // Preferred: 16-CTA cluster (128 thr/CTA) -> half the per-SM load/tail.
    // Requires the non-portable cluster-size attribute; fall back to the
    // proven 8x256 configuration if it is not granted on this chip/driver.
    cudaError_t attr_ok = cudaFuncSetAttribute(
        (const void*)recurrent_kernel<16, 128>,
        cudaFuncAttributeNonPortableClusterSizeAllowed, 1);

    cudaLaunchConfig_t cfg = {};
    cudaLaunchAttribute attrs[1];
    attrs[0].id = cudaLaunchAttributeClusterDimension;
    cfg.attrs = attrs;
    cfg.numAttrs = 1;

    if (attr_ok == cudaSuccess) {
        cfg.gridDim  = {16, 1, 1};
        cfg.blockDim = {128, 1, 1};
        attrs[0].val.clusterDim = {16, 1, 1};
        cudaError_t e = cudaLaunchKernelEx(&cfg, recurrent_kernel<16, 128>,
                                           input_bits, conn_state, state_table,
                                           conn_out, output_table, out);
        if (e == cudaSuccess) return;
        (void)cudaGetLastError();   // clear and fall through to portable config
    } else {
        (void)cudaGetLastError();
    }

    cfg.gridDim  = {8, 1, 1};
    cfg.blockDim = {256, 1, 1};
    attrs[0].val.clusterDim = {8, 1, 1};
    cudaLaunchKernelEx(&cfg, recurrent_kernel<8, 256>,
                       input_bits, conn_state, state_table,
                       conn_out, output_table, out);
}